// round 1
// baseline (speedup 1.0000x reference)
#include <cuda_runtime.h>

#define FULLM 0xffffffffu
#define NMAXP 1000000
#define VMAXP 200000

struct WP {
  const float *pe_w1,*pe_g1,*pe_b1,*pe_w2,*pe_g2,*pe_b2,*pe_w3,*pe_g3,*pe_b3;
  const float *ve_w1,*ve_g1,*ve_b1,*ve_w2,*ve_g2,*ve_b2;
  const float *fu_w,*fu_g,*fu_b;
  const float *cl_w1,*cl_g1,*cl_b1;
  const float *ax_w1,*ax_g1,*ax_b1;
  const int   *pv_raw;
};

// ---- folded weights (bn scale folded into columns) ----
static __device__ float g_w_pe1[4*32],  g_b_pe1[32];
static __device__ float g_w_pe2[32*64], g_b_pe2[64];
static __device__ float g_w_pe3[64*32], g_b_pe3[32];
static __device__ float g_w_ve1[32*32], g_b_ve1[32];
static __device__ float g_w_ve2[32*32], g_b_ve2[32];
static __device__ float g_w_fu [64*64], g_b_fu [64];
static __device__ float g_w_cl1[64*32], g_b_cl1[32];
static __device__ float g_w_ax1[32*32], g_b_ax1[32];

// ---- scratch ----
static __device__ int      g_pv_is64;
static __device__ int      g_pv[NMAXP];
static __device__ float    g_pf[32*NMAXP];       // SoA [c][N]
static __device__ unsigned g_vmax[VMAXP*32];     // row-major [V][32], uint bits of nonneg floats
static __device__ float    g_vf[VMAXP*32];       // row-major [V][32]
static __device__ float    g_fused[64*NMAXP];    // SoA [c][N]
static __device__ float    g_bsum[4*64];
static __device__ unsigned g_bcnt[4];
static __device__ float    g_gp1[4*64];          // 1 + gate

__device__ __forceinline__ void fold_w(float* dw, float* db,
    const float* W, const float* g, const float* b, int fi, int fo) {
  const float inv = 1.0f / sqrtf(1.0f + 1e-5f);
  for (int t = threadIdx.x; t < fi*fo; t += blockDim.x) dw[t] = W[t] * (g[t % fo] * inv);
  for (int t = threadIdx.x; t < fo;    t += blockDim.x) db[t] = b[t];
}

__global__ void k_prep(WP p) {
  fold_w(g_w_pe1, g_b_pe1, p.pe_w1, p.pe_g1, p.pe_b1, 4, 32);
  fold_w(g_w_pe2, g_b_pe2, p.pe_w2, p.pe_g2, p.pe_b2, 32, 64);
  fold_w(g_w_pe3, g_b_pe3, p.pe_w3, p.pe_g3, p.pe_b3, 64, 32);
  fold_w(g_w_ve1, g_b_ve1, p.ve_w1, p.ve_g1, p.ve_b1, 32, 32);
  fold_w(g_w_ve2, g_b_ve2, p.ve_w2, p.ve_g2, p.ve_b2, 32, 32);
  fold_w(g_w_fu,  g_b_fu,  p.fu_w,  p.fu_g,  p.fu_b,  64, 64);
  fold_w(g_w_cl1, g_b_cl1, p.cl_w1, p.cl_g1, p.cl_b1, 64, 32);
  fold_w(g_w_ax1, g_b_ax1, p.ax_w1, p.ax_g1, p.ax_b1, 32, 32);
  if (threadIdx.x == 0) {
    // detect int64 voxel ids: values < 2^31 => every odd 32-bit word is 0
    int z = 1;
    for (int k = 1; k < 128; k += 2) if (p.pv_raw[k] != 0) { z = 0; break; }
    g_pv_is64 = z;
  }
}

__global__ void k_init(const void* pv_raw, int N, int V) {
  int i = blockIdx.x * blockDim.x + threadIdx.x;
  if (i < N) {
    g_pv[i] = g_pv_is64 ? (int)((const long long*)pv_raw)[i]
                        : ((const int*)pv_raw)[i];
  }
  if (i < 32*V) g_vmax[i] = 0u;
  if (i < 256)  g_bsum[i] = 0.0f;
  if (i < 4)    g_bcnt[i] = 0u;
}

// ---- per-point MLP 4->32->64->32, store pf, scatter segment_max ----
__global__ void __launch_bounds__(256) k_points(const float* __restrict__ points, int N) {
  __shared__ float sw1[4*32], sb1[32], sw2[32*64], sb2[64], sw3[64*32], sb3[32];
  for (int t = threadIdx.x; t < 4*32;  t += blockDim.x) sw1[t] = g_w_pe1[t];
  for (int t = threadIdx.x; t < 32;    t += blockDim.x) sb1[t] = g_b_pe1[t];
  for (int t = threadIdx.x; t < 32*64; t += blockDim.x) sw2[t] = g_w_pe2[t];
  for (int t = threadIdx.x; t < 64;    t += blockDim.x) sb2[t] = g_b_pe2[t];
  for (int t = threadIdx.x; t < 64*32; t += blockDim.x) sw3[t] = g_w_pe3[t];
  for (int t = threadIdx.x; t < 32;    t += blockDim.x) sb3[t] = g_b_pe3[t];
  __syncthreads();
  int i = blockIdx.x * blockDim.x + threadIdx.x;
  if (i >= N) return;
  const float* pr = points + (size_t)i * 5;
  float x0 = pr[1], x1 = pr[2], x2 = pr[3], x3 = pr[4];
  float h1[32];
  #pragma unroll
  for (int o = 0; o < 32; o++) {
    float a = sb1[o] + x0*sw1[o] + x1*sw1[32+o] + x2*sw1[64+o] + x3*sw1[96+o];
    h1[o] = fmaxf(a, 0.0f);
  }
  float h2[64];
  #pragma unroll
  for (int o = 0; o < 64; o++) {
    float a = sb2[o];
    #pragma unroll
    for (int k = 0; k < 32; k++) a += h1[k] * sw2[k*64+o];
    h2[o] = fmaxf(a, 0.0f);
  }
  int pv = g_pv[i];
  unsigned* vrow = g_vmax + (size_t)pv * 32;
  #pragma unroll
  for (int o = 0; o < 32; o++) {
    float a = sb3[o];
    #pragma unroll
    for (int k = 0; k < 64; k++) a += h2[k] * sw3[k*32+o];
    a = fmaxf(a, 0.0f);
    g_pf[o*N + i] = a;                       // SoA coalesced
    atomicMax(vrow + o, __float_as_uint(a)); // nonneg float bits order-preserving
  }
}

// ---- per-voxel MLP + aux head ----
__global__ void __launch_bounds__(256) k_vox(float* __restrict__ aux_out,
                                             const float* __restrict__ ax_w2, int V) {
  __shared__ float s1[32*32], sb1v[32], s2[32*32], sb2v[32], sa[32*32], sba[32], sa2[32*20];
  __shared__ float so[256*21];
  for (int t = threadIdx.x; t < 32*32; t += blockDim.x) s1[t] = g_w_ve1[t];
  for (int t = threadIdx.x; t < 32;    t += blockDim.x) sb1v[t] = g_b_ve1[t];
  for (int t = threadIdx.x; t < 32*32; t += blockDim.x) s2[t] = g_w_ve2[t];
  for (int t = threadIdx.x; t < 32;    t += blockDim.x) sb2v[t] = g_b_ve2[t];
  for (int t = threadIdx.x; t < 32*32; t += blockDim.x) sa[t] = g_w_ax1[t];
  for (int t = threadIdx.x; t < 32;    t += blockDim.x) sba[t] = g_b_ax1[t];
  for (int t = threadIdx.x; t < 32*20; t += blockDim.x) sa2[t] = ax_w2[t];
  __syncthreads();
  int j = blockIdx.x * blockDim.x + threadIdx.x;
  bool act = j < V;
  if (act) {
    float vox[32];
    const uint4* vr = reinterpret_cast<const uint4*>(g_vmax + (size_t)j * 32);
    #pragma unroll
    for (int q = 0; q < 8; q++) {
      uint4 t = vr[q];
      vox[4*q+0] = __uint_as_float(t.x); vox[4*q+1] = __uint_as_float(t.y);
      vox[4*q+2] = __uint_as_float(t.z); vox[4*q+3] = __uint_as_float(t.w);
    }
    float v1[32];
    #pragma unroll
    for (int o = 0; o < 32; o++) {
      float a = sb1v[o];
      #pragma unroll
      for (int k = 0; k < 32; k++) a += vox[k] * s1[k*32+o];
      v1[o] = fmaxf(a, 0.0f);
    }
    float vfv[32];
    #pragma unroll
    for (int o = 0; o < 32; o++) {
      float a = sb2v[o];
      #pragma unroll
      for (int k = 0; k < 32; k++) a += v1[k] * s2[k*32+o];
      vfv[o] = fmaxf(a, 0.0f);
    }
    float4* vfr = reinterpret_cast<float4*>(g_vf + (size_t)j * 32);
    #pragma unroll
    for (int q = 0; q < 8; q++) vfr[q] = make_float4(vfv[4*q], vfv[4*q+1], vfv[4*q+2], vfv[4*q+3]);
    float ah[32];
    #pragma unroll
    for (int o = 0; o < 32; o++) {
      float a = sba[o];
      #pragma unroll
      for (int k = 0; k < 32; k++) a += v1[k] * sa[k*32+o];
      ah[o] = fmaxf(a, 0.0f);
    }
    #pragma unroll
    for (int o = 0; o < 20; o++) {
      float a = 0.0f;
      #pragma unroll
      for (int k = 0; k < 32; k++) a += ah[k] * sa2[k*20+o];
      so[threadIdx.x*21 + o] = a;
    }
  }
  __syncthreads();
  int base = blockIdx.x * blockDim.x;
  int rows = V - base; if (rows > 256) rows = 256;
  if (rows > 0)
    for (int t = threadIdx.x; t < rows*20; t += blockDim.x)
      aux_out[(size_t)base*20 + t] = so[(t/20)*21 + (t%20)];
}

// ---- gather vf, concat with pf, fuse 64->64, batch reduction ----
__global__ void __launch_bounds__(256) k_fuse(const float* __restrict__ points, int N, int V) {
  __shared__ float sw[64*64], sb[64];
  __shared__ float swsum[8][64];
  __shared__ int   swb[8];
  for (int t = threadIdx.x; t < 64*64; t += blockDim.x) sw[t] = g_w_fu[t];
  for (int t = threadIdx.x; t < 64;    t += blockDim.x) sb[t] = g_b_fu[t];
  __syncthreads();
  int i = blockIdx.x * blockDim.x + threadIdx.x;
  int lane = threadIdx.x & 31, wid = threadIdx.x >> 5;
  bool act = i < N;
  float in[64], f[64];
  int b = -1;
  if (act) {
    int pv = g_pv[i];
    const float4* vr = reinterpret_cast<const float4*>(g_vf + (size_t)pv * 32);
    #pragma unroll
    for (int q = 0; q < 8; q++) {
      float4 t = vr[q];
      in[4*q+0] = t.x; in[4*q+1] = t.y; in[4*q+2] = t.z; in[4*q+3] = t.w;
    }
    #pragma unroll
    for (int c = 0; c < 32; c++) in[32+c] = g_pf[c*N + i];
    b = (int)points[(size_t)i*5];
  } else {
    #pragma unroll
    for (int c = 0; c < 64; c++) in[c] = 0.0f;
  }
  #pragma unroll
  for (int o = 0; o < 64; o++) {
    float a = sb[o];
    #pragma unroll
    for (int k = 0; k < 64; k++) a += in[k] * sw[k*64+o];
    a = fmaxf(a, 0.0f);
    f[o] = act ? a : 0.0f;
    if (act) g_fused[o*N + i] = a;
  }
  unsigned grp = __match_any_sync(FULLM, b);
  if (grp == FULLM) {          // whole warp same batch (or whole warp inactive)
    #pragma unroll
    for (int c = 0; c < 64; c++) {
      float v = f[c];
      v += __shfl_xor_sync(FULLM, v, 16);
      v += __shfl_xor_sync(FULLM, v, 8);
      v += __shfl_xor_sync(FULLM, v, 4);
      v += __shfl_xor_sync(FULLM, v, 2);
      v += __shfl_xor_sync(FULLM, v, 1);
      if (lane == 0) swsum[wid][c] = v;
    }
    if (lane == 0) swb[wid] = b;
  } else {                      // rare: batch-boundary or partial tail warp
    if (lane == 0) swb[wid] = -1;
    if (act) {
      for (int c = 0; c < 64; c++) atomicAdd(&g_bsum[b*64 + c], f[c]);
      atomicAdd(&g_bcnt[b], 1u);
    }
  }
  __syncthreads();
  if (threadIdx.x < 64) {
    int c = threadIdx.x;
    int curb = -1; float cv = 0.0f;
    for (int w = 0; w < 8; w++) {
      int wb = swb[w];
      if (wb < 0) continue;
      if (wb != curb) { if (curb >= 0) atomicAdd(&g_bsum[curb*64 + c], cv); curb = wb; cv = 0.0f; }
      cv += swsum[w][c];
    }
    if (curb >= 0) atomicAdd(&g_bsum[curb*64 + c], cv);
  }
  if (threadIdx.x == 0) {
    int curb = -1; unsigned cc = 0;
    for (int w = 0; w < 8; w++) {
      int wb = swb[w];
      if (wb < 0) continue;
      if (wb != curb) { if (curb >= 0) atomicAdd(&g_bcnt[curb], cc); curb = wb; cc = 0; }
      cc += 32;
    }
    if (curb >= 0) atomicAdd(&g_bcnt[curb], cc);
  }
}

// ---- SE gate (tiny) ----
__global__ void k_se(const float* __restrict__ se_w1, const float* __restrict__ se_b1,
                     const float* __restrict__ se_w2, const float* __restrict__ se_b2) {
  __shared__ float mean[4*64], t1[16];
  int tid = threadIdx.x;
  int b = tid >> 6, c = tid & 63;
  mean[tid] = g_bsum[tid] / fmaxf((float)g_bcnt[b], 1.0f);
  __syncthreads();
  if (tid < 16) {
    int bb = tid >> 2, jj = tid & 3;
    float a = se_b1[jj];
    for (int k = 0; k < 64; k++) a += mean[bb*64 + k] * se_w1[k*4 + jj];
    t1[tid] = fmaxf(a, 0.0f);
  }
  __syncthreads();
  {
    float a = se_b2[c];
    #pragma unroll
    for (int jj = 0; jj < 4; jj++) a += t1[b*4 + jj] * se_w2[jj*64 + c];
    g_gp1[tid] = 1.0f + 1.0f / (1.0f + expf(-a));
  }
}

// ---- classifier head: gate-scale, 64->32->20 ----
__global__ void __launch_bounds__(256) k_out(const float* __restrict__ points,
                                             const float* __restrict__ cl_w2,
                                             float* __restrict__ out, int N) {
  __shared__ float sw1[64*32], sb1c[32], sw2[32*20], sg[4*64];
  __shared__ float so[256*21];
  for (int t = threadIdx.x; t < 64*32; t += blockDim.x) sw1[t] = g_w_cl1[t];
  for (int t = threadIdx.x; t < 32;    t += blockDim.x) sb1c[t] = g_b_cl1[t];
  for (int t = threadIdx.x; t < 32*20; t += blockDim.x) sw2[t] = cl_w2[t];
  for (int t = threadIdx.x; t < 256;   t += blockDim.x) sg[t] = g_gp1[t];
  __syncthreads();
  int i = blockIdx.x * blockDim.x + threadIdx.x;
  bool act = i < N;
  if (act) {
    int b = (int)points[(size_t)i*5];
    float f[64];
    #pragma unroll
    for (int c = 0; c < 64; c++) f[c] = g_fused[c*N + i] * sg[b*64 + c];
    float h[32];
    #pragma unroll
    for (int o = 0; o < 32; o++) {
      float a = sb1c[o];
      #pragma unroll
      for (int k = 0; k < 64; k++) a += f[k] * sw1[k*32+o];
      h[o] = fmaxf(a, 0.0f);
    }
    #pragma unroll
    for (int o = 0; o < 20; o++) {
      float a = 0.0f;
      #pragma unroll
      for (int k = 0; k < 32; k++) a += h[k] * sw2[k*20+o];
      so[threadIdx.x*21 + o] = a;
    }
  }
  __syncthreads();
  int base = blockIdx.x * blockDim.x;
  int rows = N - base; if (rows > 256) rows = 256;
  if (rows > 0)
    for (int t = threadIdx.x; t < rows*20; t += blockDim.x)
      out[(size_t)base*20 + t] = so[(t/20)*21 + (t%20)];
}

extern "C" void kernel_launch(void* const* d_in, const int* in_sizes, int n_in,
                              void* d_out, int out_size) {
  const float* points = (const float*)d_in[0];
  int N = in_sizes[0] / 5;
  int V = (out_size - N * 20) / 20;
  float* out = (float*)d_out;
  float* aux_out = out + (size_t)N * 20;

  WP wp;
  wp.pe_w1 = (const float*)d_in[2];  wp.pe_g1 = (const float*)d_in[3];  wp.pe_b1 = (const float*)d_in[4];
  wp.pe_w2 = (const float*)d_in[5];  wp.pe_g2 = (const float*)d_in[6];  wp.pe_b2 = (const float*)d_in[7];
  wp.pe_w3 = (const float*)d_in[8];  wp.pe_g3 = (const float*)d_in[9];  wp.pe_b3 = (const float*)d_in[10];
  wp.ve_w1 = (const float*)d_in[11]; wp.ve_g1 = (const float*)d_in[12]; wp.ve_b1 = (const float*)d_in[13];
  wp.ve_w2 = (const float*)d_in[14]; wp.ve_g2 = (const float*)d_in[15]; wp.ve_b2 = (const float*)d_in[16];
  wp.fu_w  = (const float*)d_in[17]; wp.fu_g  = (const float*)d_in[18]; wp.fu_b  = (const float*)d_in[19];
  wp.cl_w1 = (const float*)d_in[24]; wp.cl_g1 = (const float*)d_in[25]; wp.cl_b1 = (const float*)d_in[26];
  wp.ax_w1 = (const float*)d_in[28]; wp.ax_g1 = (const float*)d_in[29]; wp.ax_b1 = (const float*)d_in[30];
  wp.pv_raw = (const int*)d_in[1];

  k_prep<<<1, 256>>>(wp);

  int tot = 32 * V; if (N > tot) tot = N;
  k_init<<<(tot + 255) / 256, 256>>>(d_in[1], N, V);

  k_points<<<(N + 255) / 256, 256>>>(points, N);
  k_vox<<<(V + 255) / 256, 256>>>(aux_out, (const float*)d_in[31], V);
  k_fuse<<<(N + 255) / 256, 256>>>(points, N, V);
  k_se<<<1, 256>>>((const float*)d_in[20], (const float*)d_in[21],
                   (const float*)d_in[22], (const float*)d_in[23]);
  k_out<<<(N + 255) / 256, 256>>>(points, (const float*)d_in[27], out, N);
}